// round 9
// baseline (speedup 1.0000x reference)
#include <cuda_runtime.h>

// Shapes (fixed by the problem)
#define B_   8
#define C_   256
#define MID_ 16
#define H_   128
#define W_   128
#define HW_  (H_*W_)      // 16384
#define PADK 3

// Scratch (no allocs allowed)
__device__ float g_xlow0[B_*MID_*HW_];   // 8 MB : partial sum c=0..127
__device__ float g_xlow1[B_*MID_*HW_];   // 8 MB : partial sum c=128..255
__device__ float g_outlow[B_*MID_*HW_];  // 8 MB
__device__ float g_wh[B_*HW_];           // 0.5 MB : cos^2(angle)

// ---- packed f32x2 helpers (sm_103a) ----
static __device__ __forceinline__ unsigned long long pack2(float lo, float hi) {
    unsigned long long r;
    asm("mov.b64 %0, {%1, %2};" : "=l"(r) : "f"(lo), "f"(hi));
    return r;
}
static __device__ __forceinline__ void unpack2(unsigned long long v, float& lo, float& hi) {
    asm("mov.b64 {%0, %1}, %2;" : "=f"(lo), "=f"(hi) : "l"(v));
}
static __device__ __forceinline__ unsigned long long ffma2(
    unsigned long long a, unsigned long long b, unsigned long long c) {
    unsigned long long d;
    asm("fma.rn.f32x2 %0, %1, %2, %3;" : "=l"(d) : "l"(a), "l"(b), "l"(c));
    return d;
}

// ---------------------------------------------------------------------------
// K1: partial x_low over a 128-channel half.  2 px/thread, 16-deep LDG batch.
// grid (512, 2): x = pixel pairs (128 thr x 2 px), y = c-half.
// ---------------------------------------------------------------------------
__global__ __launch_bounds__(128, 6) void k_reduce(const float* __restrict__ x,
                                                   const float* __restrict__ angle,
                                                   const float* __restrict__ wr) {
    __shared__ unsigned long long s_w[128*8];   // 8 KB (this c-half)
    int tid   = threadIdx.x;
    int cz    = blockIdx.y;                     // 0 or 1
    int cbase = cz * 128;

    // pack weights for this half: thread t owns channel cbase+t
    {
        int c = cbase + tid;
        float wv[16];
        #pragma unroll
        for (int m = 0; m < 16; m++) wv[m] = wr[m * C_ + c];
        #pragma unroll
        for (int q = 0; q < 8; q++)
            s_w[tid * 8 + q] = pack2(wv[2*q], wv[2*q+1]);
    }
    __syncthreads();

    int t  = blockIdx.x * 128 + tid;     // 0..65535
    int pp = t * 2;                      // pixel pair base
    int b  = pp >> 14;
    int hw = pp & (HW_ - 1);

    const float* xp = x + (long)b * C_ * HW_ + (long)cbase * HW_ + hw;

    unsigned long long aA[8], aB[8];
    #pragma unroll
    for (int q = 0; q < 8; q++) { aA[q]=0ULL; aB[q]=0ULL; }

    #pragma unroll
    for (int c0 = 0; c0 < 128; c0 += 16) {
        float2 vv[16];
        #pragma unroll
        for (int u = 0; u < 16; u++)
            vv[u] = __ldcs(reinterpret_cast<const float2*>(xp + (long)(c0 + u) * HW_));
        #pragma unroll
        for (int u = 0; u < 16; u++) {
            unsigned long long vA = pack2(vv[u].x, vv[u].x);
            unsigned long long vB = pack2(vv[u].y, vv[u].y);
            const ulonglong2* wrow =
                reinterpret_cast<const ulonglong2*>(&s_w[(c0 + u) * 8]);
            ulonglong2 w01 = wrow[0];
            ulonglong2 w23 = wrow[1];
            ulonglong2 w45 = wrow[2];
            ulonglong2 w67 = wrow[3];
            aA[0]=ffma2(vA,w01.x,aA[0]); aB[0]=ffma2(vB,w01.x,aB[0]);
            aA[1]=ffma2(vA,w01.y,aA[1]); aB[1]=ffma2(vB,w01.y,aB[1]);
            aA[2]=ffma2(vA,w23.x,aA[2]); aB[2]=ffma2(vB,w23.x,aB[2]);
            aA[3]=ffma2(vA,w23.y,aA[3]); aB[3]=ffma2(vB,w23.y,aB[3]);
            aA[4]=ffma2(vA,w45.x,aA[4]); aB[4]=ffma2(vB,w45.x,aB[4]);
            aA[5]=ffma2(vA,w45.y,aA[5]); aB[5]=ffma2(vB,w45.y,aB[5]);
            aA[6]=ffma2(vA,w67.x,aA[6]); aB[6]=ffma2(vB,w67.x,aB[6]);
            aA[7]=ffma2(vA,w67.y,aA[7]); aB[7]=ffma2(vB,w67.y,aB[7]);
        }
    }

    float* op = (cz ? g_xlow1 : g_xlow0) + (long)b * MID_ * HW_ + hw;
    #pragma unroll
    for (int q = 0; q < 8; q++) {
        float A0,A1,B0,B1;
        unpack2(aA[q], A0, A1);
        unpack2(aB[q], B0, B1);
        *reinterpret_cast<float2*>(op + (long)(2*q)   * HW_) = make_float2(A0,B0);
        *reinterpret_cast<float2*>(op + (long)(2*q+1) * HW_) = make_float2(A1,B1);
    }

    // wh = cos^2(angle), once per pixel (conv consumes it 16x); only c-half 0
    if (cz == 0) {
        float2 a2 = *reinterpret_cast<const float2*>(angle + b * HW_ + hw);
        float c0v = cosf(a2.x), c1v = cosf(a2.y);
        *reinterpret_cast<float2*>(g_wh + pp) = make_float2(c0v*c0v, c1v*c1v);
    }
}

// ---------------------------------------------------------------------------
// K2: out_low = wh*(x_low (*) BASE_H) + (1-wh)*(x_low (*) BASE_V)
// x_low = g_xlow0 + g_xlow1 (summed in halo load). Separable, literal taps.
// ---------------------------------------------------------------------------
#define TILE_H 16
#define TILE_W 32
#define HALO_H (TILE_H + 6)          // 22
#define HALO_W (TILE_W + 6)          // 38

// f(a)=exp(-a^2/12.5), g(a)=exp(-a^2/2), a=-3..3
#define F0 0.48675225595997157f
#define F1 0.7261490370736909f
#define F2 0.9231163463866358f
#define F3 1.0f
#define G0 0.011108996538242306f
#define G1 0.1353352832366127f
#define G2 0.6065306597126334f
#define G3 1.0f
#define SUMF (F3 + 2.0f*(F0 + F1 + F2))
#define SUMG (G3 + 2.0f*(G0 + G1 + G2))
#define INVS (1.0f/(SUMF*SUMG + 1e-8f))

__global__ __launch_bounds__(TILE_H*TILE_W) void k_conv() {
    __shared__ float  s_t[HALO_H * HALO_W];          // raw tile + halo
    __shared__ float2 s_hf[HALO_H * TILE_W];         // (Hg, Hf) per position

    const float Fk[7] = {F0, F1, F2, F3, F2, F1, F0};
    const float Gk[7] = {G0, G1, G2, G3, G2, G1, G0};

    int tid = threadIdx.y * TILE_W + threadIdx.x;
    int bz  = blockIdx.z;             // b*16 + m
    int b   = bz >> 4;
    int h0  = blockIdx.y * TILE_H;
    int w0  = blockIdx.x * TILE_W;
    int h   = h0 + threadIdx.y, w = w0 + threadIdx.x;

    float wh = g_wh[b * HW_ + h * W_ + w];

    // load halo tile with reflect padding, summing the two c-half partials
    const float* xl0 = g_xlow0 + (long)bz * HW_;
    const float* xl1 = g_xlow1 + (long)bz * HW_;
    for (int idx = tid; idx < HALO_H * HALO_W; idx += TILE_H * TILE_W) {
        int hh = idx / HALO_W, ww = idx - hh * HALO_W;
        int gh = h0 + hh - PADK;
        int gw = w0 + ww - PADK;
        gh = gh < 0 ? -gh : (gh > H_-1 ? 2*(H_-1) - gh : gh);
        gw = gw < 0 ? -gw : (gw > W_-1 ? 2*(W_-1) - gw : gw);
        int o = gh * W_ + gw;
        s_t[idx] = xl0[o] + xl1[o];
    }
    __syncthreads();

    // stage 1: horizontal 1-D passes (g and f)
    for (int idx = tid; idx < HALO_H * TILE_W; idx += TILE_H * TILE_W) {
        int r = idx >> 5;            // row 0..21 (TILE_W == 32)
        int xw = idx & 31;
        const float* row = s_t + r * HALO_W + xw;
        float hg = 0.f, hf = 0.f;
        #pragma unroll
        for (int j = 0; j < 7; j++) {
            float v = row[j];
            hg = fmaf(v, Gk[j], hg);
            hf = fmaf(v, Fk[j], hf);
        }
        s_hf[idx] = make_float2(hg, hf);
    }
    __syncthreads();

    // stage 2: vertical 1-D passes (f on Hg, g on Hf), inv folded in
    float aH = 0.f, aV = 0.f;
    #pragma unroll
    for (int i = 0; i < 7; i++) {
        float2 hv = s_hf[(threadIdx.y + i) * TILE_W + threadIdx.x];
        aH = fmaf(hv.x, Fk[i] * INVS, aH);
        aV = fmaf(hv.y, Gk[i] * INVS, aV);
    }

    g_outlow[(long)bz * HW_ + h * W_ + w] = wh * aH + (1.f - wh) * aV;
}

// ---------------------------------------------------------------------------
// K3: out[b,c,hw] = sum_m out_low[b,m,hw] * w_expand[c,m]
// 4 px/thread (STG.128) + c-split x4; __launch_bounds__(128,6) to force
// >=6 resident blocks (24 warps/SM) instead of the 94-reg 5-block cap.
// Weights are a direct u64 reinterpret of row-major w_expand.
// ---------------------------------------------------------------------------
__global__ __launch_bounds__(128, 6) void k_expand(float* __restrict__ out,
                                                   const float* __restrict__ we) {
    __shared__ unsigned long long s_w[64*8];    // 4 KB (this block's c-quarter)
    int tid = threadIdx.x;
    int cbase = blockIdx.y * 64;                // 0,64,128,192
    {
        const unsigned long long* we64 =
            reinterpret_cast<const unsigned long long*>(we);
        #pragma unroll
        for (int i = tid; i < 64*8; i += 128) s_w[i] = we64[cbase*8 + i];
    }
    __syncthreads();

    int t  = blockIdx.x * 128 + tid;     // 0..32767
    int pp = t * 4;                      // pixel quad base
    int b  = pp >> 14;
    int hw = pp & (HW_ - 1);

    const float* olp = g_outlow + (long)b * MID_ * HW_ + hw;

    unsigned long long olA[8], olB[8], olC[8], olD[8];
    #pragma unroll
    for (int q = 0; q < 8; q++) {
        float4 e = *reinterpret_cast<const float4*>(olp + (long)(2*q)   * HW_);
        float4 o = *reinterpret_cast<const float4*>(olp + (long)(2*q+1) * HW_);
        olA[q] = pack2(e.x, o.x);
        olB[q] = pack2(e.y, o.y);
        olC[q] = pack2(e.z, o.z);
        olD[q] = pack2(e.w, o.w);
    }

    float* op = out + (long)b * C_ * HW_ + (long)cbase * HW_ + hw;

    for (int c = 0; c < 64; c++) {
        const ulonglong2* wrow = reinterpret_cast<const ulonglong2*>(&s_w[c*8]);
        ulonglong2 w01 = wrow[0];
        ulonglong2 w23 = wrow[1];
        ulonglong2 w45 = wrow[2];
        ulonglong2 w67 = wrow[3];
        unsigned long long a0=0ULL, a1=0ULL, a2=0ULL, a3=0ULL;
        a0=ffma2(olA[0],w01.x,a0); a1=ffma2(olB[0],w01.x,a1); a2=ffma2(olC[0],w01.x,a2); a3=ffma2(olD[0],w01.x,a3);
        a0=ffma2(olA[1],w01.y,a0); a1=ffma2(olB[1],w01.y,a1); a2=ffma2(olC[1],w01.y,a2); a3=ffma2(olD[1],w01.y,a3);
        a0=ffma2(olA[2],w23.x,a0); a1=ffma2(olB[2],w23.x,a1); a2=ffma2(olC[2],w23.x,a2); a3=ffma2(olD[2],w23.x,a3);
        a0=ffma2(olA[3],w23.y,a0); a1=ffma2(olB[3],w23.y,a1); a2=ffma2(olC[3],w23.y,a2); a3=ffma2(olD[3],w23.y,a3);
        a0=ffma2(olA[4],w45.x,a0); a1=ffma2(olB[4],w45.x,a1); a2=ffma2(olC[4],w45.x,a2); a3=ffma2(olD[4],w45.x,a3);
        a0=ffma2(olA[5],w45.y,a0); a1=ffma2(olB[5],w45.y,a1); a2=ffma2(olC[5],w45.y,a2); a3=ffma2(olD[5],w45.y,a3);
        a0=ffma2(olA[6],w67.x,a0); a1=ffma2(olB[6],w67.x,a1); a2=ffma2(olC[6],w67.x,a2); a3=ffma2(olD[6],w67.x,a3);
        a0=ffma2(olA[7],w67.y,a0); a1=ffma2(olB[7],w67.y,a1); a2=ffma2(olC[7],w67.y,a2); a3=ffma2(olD[7],w67.y,a3);
        float l0,h0v,l1,h1v,l2,h2v,l3,h3v;
        unpack2(a0, l0, h0v);
        unpack2(a1, l1, h1v);
        unpack2(a2, l2, h2v);
        unpack2(a3, l3, h3v);
        float4 r = make_float4(l0+h0v, l1+h1v, l2+h2v, l3+h3v);
        __stcs(reinterpret_cast<float4*>(op + (long)c * HW_), r);
    }
}

// ---------------------------------------------------------------------------
extern "C" void kernel_launch(void* const* d_in, const int* in_sizes, int n_in,
                              void* d_out, int out_size) {
    const float* x      = (const float*)d_in[0];   // (8,256,128,128)
    const float* angle  = (const float*)d_in[1];   // (8,128,128)
    const float* wr     = (const float*)d_in[2];   // (16,256)
    const float* we     = (const float*)d_in[3];   // (256,16)
    float* out          = (float*)d_out;           // (8,256,128,128)

    (void)in_sizes; (void)n_in; (void)out_size;

    dim3 rgrid(512, 2);                            // pixel pairs x c-halves
    k_reduce<<<rgrid, 128>>>(x, angle, wr);        // 1024 blocks

    dim3 cgrid(W_/TILE_W, H_/TILE_H, B_*MID_);     // (4, 8, 128)
    dim3 cblk(TILE_W, TILE_H);
    k_conv<<<cgrid, cblk>>>();

    dim3 egrid(256, 4);                            // pixel quads x c-quarters
    k_expand<<<egrid, 128>>>(out, we);             // 1024 blocks
}

// round 10
// speedup vs baseline: 1.0808x; 1.0808x over previous
#include <cuda_runtime.h>

// Shapes (fixed by the problem)
#define B_   8
#define C_   256
#define MID_ 16
#define H_   128
#define W_   128
#define HW_  (H_*W_)      // 16384
#define PADK 3

// Scratch (no allocs allowed)
__device__ float g_xlow0[B_*MID_*HW_];   // 8 MB : partial sum c=0..127
__device__ float g_xlow1[B_*MID_*HW_];   // 8 MB : partial sum c=128..255
__device__ float g_outlow[B_*MID_*HW_];  // 8 MB
__device__ float g_wh[B_*HW_];           // 0.5 MB : cos^2(angle)

// ---- packed f32x2 helpers (sm_103a) ----
static __device__ __forceinline__ unsigned long long pack2(float lo, float hi) {
    unsigned long long r;
    asm("mov.b64 %0, {%1, %2};" : "=l"(r) : "f"(lo), "f"(hi));
    return r;
}
static __device__ __forceinline__ void unpack2(unsigned long long v, float& lo, float& hi) {
    asm("mov.b64 {%0, %1}, %2;" : "=f"(lo), "=f"(hi) : "l"(v));
}
static __device__ __forceinline__ unsigned long long ffma2(
    unsigned long long a, unsigned long long b, unsigned long long c) {
    unsigned long long d;
    asm("fma.rn.f32x2 %0, %1, %2, %3;" : "=l"(d) : "l"(a), "l"(b), "l"(c));
    return d;
}

// ---------------------------------------------------------------------------
// K1: partial x_low over a 128-channel half.  2 px/thread, 8-deep LDG batch.
// 64-thread blocks: 60 regs x 64 thr packs 16 blocks/SM (32 warps, 50% occ).
// grid (1024, 2): x = pixel pairs (64 thr x 2 px), y = c-half.
// ---------------------------------------------------------------------------
__global__ __launch_bounds__(64) void k_reduce(const float* __restrict__ x,
                                               const float* __restrict__ angle,
                                               const float* __restrict__ wr) {
    __shared__ unsigned long long s_w[128*8];   // 8 KB (this c-half)
    int tid   = threadIdx.x;
    int cz    = blockIdx.y;                     // 0 or 1
    int cbase = cz * 128;

    // pack weights for this half: each thread owns 2 channels
    #pragma unroll
    for (int cc = tid; cc < 128; cc += 64) {
        int c = cbase + cc;
        float wv[16];
        #pragma unroll
        for (int m = 0; m < 16; m++) wv[m] = wr[m * C_ + c];
        #pragma unroll
        for (int q = 0; q < 8; q++)
            s_w[cc * 8 + q] = pack2(wv[2*q], wv[2*q+1]);
    }
    __syncthreads();

    int t  = blockIdx.x * 64 + tid;      // 0..65535
    int pp = t * 2;                      // pixel pair base
    int b  = pp >> 14;
    int hw = pp & (HW_ - 1);

    const float* xp = x + (long)b * C_ * HW_ + (long)cbase * HW_ + hw;

    unsigned long long aA[8], aB[8];
    #pragma unroll
    for (int q = 0; q < 8; q++) { aA[q]=0ULL; aB[q]=0ULL; }

    #pragma unroll
    for (int c0 = 0; c0 < 128; c0 += 8) {
        float2 vv[8];
        #pragma unroll
        for (int u = 0; u < 8; u++)
            vv[u] = __ldcs(reinterpret_cast<const float2*>(xp + (long)(c0 + u) * HW_));
        #pragma unroll
        for (int u = 0; u < 8; u++) {
            unsigned long long vA = pack2(vv[u].x, vv[u].x);
            unsigned long long vB = pack2(vv[u].y, vv[u].y);
            const ulonglong2* wrow =
                reinterpret_cast<const ulonglong2*>(&s_w[(c0 + u) * 8]);
            ulonglong2 w01 = wrow[0];
            ulonglong2 w23 = wrow[1];
            ulonglong2 w45 = wrow[2];
            ulonglong2 w67 = wrow[3];
            aA[0]=ffma2(vA,w01.x,aA[0]); aB[0]=ffma2(vB,w01.x,aB[0]);
            aA[1]=ffma2(vA,w01.y,aA[1]); aB[1]=ffma2(vB,w01.y,aB[1]);
            aA[2]=ffma2(vA,w23.x,aA[2]); aB[2]=ffma2(vB,w23.x,aB[2]);
            aA[3]=ffma2(vA,w23.y,aA[3]); aB[3]=ffma2(vB,w23.y,aB[3]);
            aA[4]=ffma2(vA,w45.x,aA[4]); aB[4]=ffma2(vB,w45.x,aB[4]);
            aA[5]=ffma2(vA,w45.y,aA[5]); aB[5]=ffma2(vB,w45.y,aB[5]);
            aA[6]=ffma2(vA,w67.x,aA[6]); aB[6]=ffma2(vB,w67.x,aB[6]);
            aA[7]=ffma2(vA,w67.y,aA[7]); aB[7]=ffma2(vB,w67.y,aB[7]);
        }
    }

    float* op = (cz ? g_xlow1 : g_xlow0) + (long)b * MID_ * HW_ + hw;
    #pragma unroll
    for (int q = 0; q < 8; q++) {
        float A0,A1,B0,B1;
        unpack2(aA[q], A0, A1);
        unpack2(aB[q], B0, B1);
        *reinterpret_cast<float2*>(op + (long)(2*q)   * HW_) = make_float2(A0,B0);
        *reinterpret_cast<float2*>(op + (long)(2*q+1) * HW_) = make_float2(A1,B1);
    }

    // wh = cos^2(angle), once per pixel (conv consumes it 16x); only c-half 0
    if (cz == 0) {
        float2 a2 = *reinterpret_cast<const float2*>(angle + b * HW_ + hw);
        float c0v = cosf(a2.x), c1v = cosf(a2.y);
        *reinterpret_cast<float2*>(g_wh + pp) = make_float2(c0v*c0v, c1v*c1v);
    }
}

// ---------------------------------------------------------------------------
// K2: out_low = wh*(x_low (*) BASE_H) + (1-wh)*(x_low (*) BASE_V)
// x_low = g_xlow0 + g_xlow1 (summed in halo load). Separable, literal taps.
// ---------------------------------------------------------------------------
#define TILE_H 16
#define TILE_W 32
#define HALO_H (TILE_H + 6)          // 22
#define HALO_W (TILE_W + 6)          // 38

// f(a)=exp(-a^2/12.5), g(a)=exp(-a^2/2), a=-3..3
#define F0 0.48675225595997157f
#define F1 0.7261490370736909f
#define F2 0.9231163463866358f
#define F3 1.0f
#define G0 0.011108996538242306f
#define G1 0.1353352832366127f
#define G2 0.6065306597126334f
#define G3 1.0f
#define SUMF (F3 + 2.0f*(F0 + F1 + F2))
#define SUMG (G3 + 2.0f*(G0 + G1 + G2))
#define INVS (1.0f/(SUMF*SUMG + 1e-8f))

__global__ __launch_bounds__(TILE_H*TILE_W) void k_conv() {
    __shared__ float  s_t[HALO_H * HALO_W];          // raw tile + halo
    __shared__ float2 s_hf[HALO_H * TILE_W];         // (Hg, Hf) per position

    const float Fk[7] = {F0, F1, F2, F3, F2, F1, F0};
    const float Gk[7] = {G0, G1, G2, G3, G2, G1, G0};

    int tid = threadIdx.y * TILE_W + threadIdx.x;
    int bz  = blockIdx.z;             // b*16 + m
    int b   = bz >> 4;
    int h0  = blockIdx.y * TILE_H;
    int w0  = blockIdx.x * TILE_W;
    int h   = h0 + threadIdx.y, w = w0 + threadIdx.x;

    float wh = g_wh[b * HW_ + h * W_ + w];

    // load halo tile with reflect padding, summing the two c-half partials
    const float* xl0 = g_xlow0 + (long)bz * HW_;
    const float* xl1 = g_xlow1 + (long)bz * HW_;
    for (int idx = tid; idx < HALO_H * HALO_W; idx += TILE_H * TILE_W) {
        int hh = idx / HALO_W, ww = idx - hh * HALO_W;
        int gh = h0 + hh - PADK;
        int gw = w0 + ww - PADK;
        gh = gh < 0 ? -gh : (gh > H_-1 ? 2*(H_-1) - gh : gh);
        gw = gw < 0 ? -gw : (gw > W_-1 ? 2*(W_-1) - gw : gw);
        int o = gh * W_ + gw;
        s_t[idx] = xl0[o] + xl1[o];
    }
    __syncthreads();

    // stage 1: horizontal 1-D passes (g and f)
    for (int idx = tid; idx < HALO_H * TILE_W; idx += TILE_H * TILE_W) {
        int r = idx >> 5;            // row 0..21 (TILE_W == 32)
        int xw = idx & 31;
        const float* row = s_t + r * HALO_W + xw;
        float hg = 0.f, hf = 0.f;
        #pragma unroll
        for (int j = 0; j < 7; j++) {
            float v = row[j];
            hg = fmaf(v, Gk[j], hg);
            hf = fmaf(v, Fk[j], hf);
        }
        s_hf[idx] = make_float2(hg, hf);
    }
    __syncthreads();

    // stage 2: vertical 1-D passes (f on Hg, g on Hf), inv folded in
    float aH = 0.f, aV = 0.f;
    #pragma unroll
    for (int i = 0; i < 7; i++) {
        float2 hv = s_hf[(threadIdx.y + i) * TILE_W + threadIdx.x];
        aH = fmaf(hv.x, Fk[i] * INVS, aH);
        aV = fmaf(hv.y, Gk[i] * INVS, aV);
    }

    g_outlow[(long)bz * HW_ + h * W_ + w] = wh * aH + (1.f - wh) * aV;
}

// ---------------------------------------------------------------------------
// K3: out[b,c,hw] = sum_m out_low[b,m,hw] * w_expand[c,m]
// 4 px/thread (STG.128) + c-split x4.  64-thread blocks: 94 regs packs
// ~10 blocks/SM (20 warps) vs 5x128 before.  grid (512, 4) = 2048 blocks.
// Weights are a direct u64 reinterpret of row-major w_expand.
// ---------------------------------------------------------------------------
__global__ __launch_bounds__(64) void k_expand(float* __restrict__ out,
                                               const float* __restrict__ we) {
    __shared__ unsigned long long s_w[64*8];    // 4 KB (this block's c-quarter)
    int tid = threadIdx.x;
    int cbase = blockIdx.y * 64;                // 0,64,128,192
    {
        const unsigned long long* we64 =
            reinterpret_cast<const unsigned long long*>(we);
        #pragma unroll
        for (int i = tid; i < 64*8; i += 64) s_w[i] = we64[cbase*8 + i];
    }
    __syncthreads();

    int t  = blockIdx.x * 64 + tid;      // 0..32767
    int pp = t * 4;                      // pixel quad base
    int b  = pp >> 14;
    int hw = pp & (HW_ - 1);

    const float* olp = g_outlow + (long)b * MID_ * HW_ + hw;

    unsigned long long olA[8], olB[8], olC[8], olD[8];
    #pragma unroll
    for (int q = 0; q < 8; q++) {
        float4 e = *reinterpret_cast<const float4*>(olp + (long)(2*q)   * HW_);
        float4 o = *reinterpret_cast<const float4*>(olp + (long)(2*q+1) * HW_);
        olA[q] = pack2(e.x, o.x);
        olB[q] = pack2(e.y, o.y);
        olC[q] = pack2(e.z, o.z);
        olD[q] = pack2(e.w, o.w);
    }

    float* op = out + (long)b * C_ * HW_ + (long)cbase * HW_ + hw;

    #pragma unroll 2
    for (int c = 0; c < 64; c++) {
        const ulonglong2* wrow = reinterpret_cast<const ulonglong2*>(&s_w[c*8]);
        ulonglong2 w01 = wrow[0];
        ulonglong2 w23 = wrow[1];
        ulonglong2 w45 = wrow[2];
        ulonglong2 w67 = wrow[3];
        unsigned long long a0=0ULL, a1=0ULL, a2=0ULL, a3=0ULL;
        a0=ffma2(olA[0],w01.x,a0); a1=ffma2(olB[0],w01.x,a1); a2=ffma2(olC[0],w01.x,a2); a3=ffma2(olD[0],w01.x,a3);
        a0=ffma2(olA[1],w01.y,a0); a1=ffma2(olB[1],w01.y,a1); a2=ffma2(olC[1],w01.y,a2); a3=ffma2(olD[1],w01.y,a3);
        a0=ffma2(olA[2],w23.x,a0); a1=ffma2(olB[2],w23.x,a1); a2=ffma2(olC[2],w23.x,a2); a3=ffma2(olD[2],w23.x,a3);
        a0=ffma2(olA[3],w23.y,a0); a1=ffma2(olB[3],w23.y,a1); a2=ffma2(olC[3],w23.y,a2); a3=ffma2(olD[3],w23.y,a3);
        a0=ffma2(olA[4],w45.x,a0); a1=ffma2(olB[4],w45.x,a1); a2=ffma2(olC[4],w45.x,a2); a3=ffma2(olD[4],w45.x,a3);
        a0=ffma2(olA[5],w45.y,a0); a1=ffma2(olB[5],w45.y,a1); a2=ffma2(olC[5],w45.y,a2); a3=ffma2(olD[5],w45.y,a3);
        a0=ffma2(olA[6],w67.x,a0); a1=ffma2(olB[6],w67.x,a1); a2=ffma2(olC[6],w67.x,a2); a3=ffma2(olD[6],w67.x,a3);
        a0=ffma2(olA[7],w67.y,a0); a1=ffma2(olB[7],w67.y,a1); a2=ffma2(olC[7],w67.y,a2); a3=ffma2(olD[7],w67.y,a3);
        float l0,h0v,l1,h1v,l2,h2v,l3,h3v;
        unpack2(a0, l0, h0v);
        unpack2(a1, l1, h1v);
        unpack2(a2, l2, h2v);
        unpack2(a3, l3, h3v);
        float4 r = make_float4(l0+h0v, l1+h1v, l2+h2v, l3+h3v);
        __stcs(reinterpret_cast<float4*>(op + (long)c * HW_), r);
    }
}

// ---------------------------------------------------------------------------
extern "C" void kernel_launch(void* const* d_in, const int* in_sizes, int n_in,
                              void* d_out, int out_size) {
    const float* x      = (const float*)d_in[0];   // (8,256,128,128)
    const float* angle  = (const float*)d_in[1];   // (8,128,128)
    const float* wr     = (const float*)d_in[2];   // (16,256)
    const float* we     = (const float*)d_in[3];   // (256,16)
    float* out          = (float*)d_out;           // (8,256,128,128)

    (void)in_sizes; (void)n_in; (void)out_size;

    dim3 rgrid(1024, 2);                           // pixel pairs x c-halves
    k_reduce<<<rgrid, 64>>>(x, angle, wr);         // 2048 blocks

    dim3 cgrid(W_/TILE_W, H_/TILE_H, B_*MID_);     // (4, 8, 128)
    dim3 cblk(TILE_W, TILE_H);
    k_conv<<<cgrid, cblk>>>();

    dim3 egrid(512, 4);                            // pixel quads x c-quarters
    k_expand<<<egrid, 64>>>(out, we);              // 2048 blocks
}